// round 1
// baseline (speedup 1.0000x reference)
#include <cuda_runtime.h>
#include <cuda_bf16.h>
#include <cstdint>

#define H 128
#define DI 64
#define MAX_N 50000
#define MAX_M 20000
#define MAX_E 1000000

// ---------------- scratch (no allocations allowed) ----------------
__device__ float g_pmsg[MAX_M * H];   // 10.24 MB
__device__ float g_imsg[MAX_N * H];   // 25.6 MB
__device__ int   g_iidx[MAX_E];
__device__ int   g_pidx[MAX_E];
__device__ int   g_is64;

// ---------------- index dtype detection + decode ----------------
// If the harness serialized int64 indices (values < 2^32), every high 32-bit
// word is 0. If it serialized int32, the "high words" are real indices,
// nonzero with prob ~1-1/50000 each. Deterministic for fixed input data.
__global__ void detect_kernel(const unsigned long long* __restrict__ raw, int nsamp) {
    __shared__ int any;
    if (threadIdx.x == 0) any = 0;
    __syncthreads();
    int found = 0;
    for (int i = threadIdx.x; i < nsamp; i += blockDim.x)
        if ((raw[i] >> 32) != 0ULL) found = 1;
    if (found) atomicExch(&any, 1);
    __syncthreads();
    if (threadIdx.x == 0) g_is64 = any ? 0 : 1;
}

__global__ void convert_kernel(const void* __restrict__ iraw,
                               const void* __restrict__ praw, int E) {
    int t = blockIdx.x * blockDim.x + threadIdx.x;
    if (t >= E) return;
    if (g_is64) {
        g_iidx[t] = (int)((const long long*)iraw)[t];
        g_pidx[t] = (int)((const long long*)praw)[t];
    } else {
        g_iidx[t] = ((const int*)iraw)[t];
        g_pidx[t] = ((const int*)praw)[t];
    }
}

// ---------------- zero ----------------
__global__ void zero_kernel(float* __restrict__ p, int n4) {
    int i = blockIdx.x * blockDim.x + threadIdx.x;
    if (i < n4) ((float4*)p)[i] = make_float4(0.f, 0.f, 0.f, 0.f);
}

// ---------------- edge scatter-add: dst[didx[e]] += src[sidx[e]] ----------------
// one warp per edge, float4 gather + red.global.add.v4.f32
__global__ __launch_bounds__(256)
void scatter_kernel(const float* __restrict__ src, float* __restrict__ dst,
                    const int* __restrict__ sidx, const int* __restrict__ didx,
                    int E) {
    int e = (int)((blockIdx.x * blockDim.x + threadIdx.x) >> 5);
    if (e >= E) return;
    int lane = threadIdx.x & 31;
    int s = __ldg(sidx + e);
    int d = __ldg(didx + e);
    float4 v = *(const float4*)(src + (size_t)s * H + lane * 4);
    float* dp = dst + (size_t)d * H + lane * 4;
    asm volatile("red.global.add.v4.f32 [%0], {%1,%2,%3,%4};"
                 :: "l"(dp), "f"(v.x), "f"(v.y), "f"(v.z), "f"(v.w)
                 : "memory");
}

// ---------------- SGEMM: C = relu(A[n,K] @ W[K,128] + b)   (FUSED: relu(C + that)) ----------------
template<int K, bool FUSED>
__global__ __launch_bounds__(256, 2)
void gemm_kernel(const float* __restrict__ A, const float* __restrict__ W,
                 const float* __restrict__ bias, float* __restrict__ C, int n) {
    constexpr int BM = 128, BK = 16;
    __shared__ float As[BK][BM + 4];   // +4 pad: avoid bank conflicts on transposed store
    __shared__ float Ws[BK][H];

    const int tid = threadIdx.x;
    const int row0 = blockIdx.x * BM;
    const int tx = tid & 15;   // col group  (8 cols each)
    const int ty = tid >> 4;   // row group  (8 rows each)

    float acc[8][8];
#pragma unroll
    for (int i = 0; i < 8; i++)
#pragma unroll
        for (int j = 0; j < 8; j++) acc[i][j] = 0.f;

    for (int k0 = 0; k0 < K; k0 += BK) {
        // load A tile: 128 rows x 16 k = 512 float4 by 256 threads
#pragma unroll
        for (int l = 0; l < 2; l++) {
            int f = tid + l * 256;
            int r = f >> 2;      // row 0..127
            int c4 = f & 3;      // float4 slot within 16 k
            int grow = row0 + r;
            float4 v = make_float4(0.f, 0.f, 0.f, 0.f);
            if (grow < n)
                v = *(const float4*)(A + (size_t)grow * K + k0 + c4 * 4);
            As[c4 * 4 + 0][r] = v.x;
            As[c4 * 4 + 1][r] = v.y;
            As[c4 * 4 + 2][r] = v.z;
            As[c4 * 4 + 3][r] = v.w;
        }
        // load W tile: 16 rows x 128 cols = 512 float4
#pragma unroll
        for (int l = 0; l < 2; l++) {
            int f = tid + l * 256;
            int r = f >> 5;      // k-row 0..15
            int c4 = f & 31;     // float4 col slot
            *(float4*)&Ws[r][c4 * 4] = *(const float4*)(W + (size_t)(k0 + r) * H + c4 * 4);
        }
        __syncthreads();

#pragma unroll
        for (int k = 0; k < BK; k++) {
            float a[8], w[8];
            *(float4*)&a[0] = *(const float4*)&As[k][ty * 8 + 0];
            *(float4*)&a[4] = *(const float4*)&As[k][ty * 8 + 4];
            *(float4*)&w[0] = *(const float4*)&Ws[k][tx * 8 + 0];
            *(float4*)&w[4] = *(const float4*)&Ws[k][tx * 8 + 4];
#pragma unroll
            for (int i = 0; i < 8; i++)
#pragma unroll
                for (int j = 0; j < 8; j++)
                    acc[i][j] = fmaf(a[i], w[j], acc[i][j]);
        }
        __syncthreads();
    }

    // epilogue
    float bj[8];
    *(float4*)&bj[0] = *(const float4*)&bias[tx * 8 + 0];
    *(float4*)&bj[4] = *(const float4*)&bias[tx * 8 + 4];
#pragma unroll
    for (int i = 0; i < 8; i++) {
        int grow = row0 + ty * 8 + i;
        if (grow >= n) continue;
        float* crow = C + (size_t)grow * H + tx * 8;
#pragma unroll
        for (int j = 0; j < 8; j += 4) {
            float4 o;
            o.x = fmaxf(acc[i][j + 0] + bj[j + 0], 0.f);
            o.y = fmaxf(acc[i][j + 1] + bj[j + 1], 0.f);
            o.z = fmaxf(acc[i][j + 2] + bj[j + 2], 0.f);
            o.w = fmaxf(acc[i][j + 3] + bj[j + 3], 0.f);
            if (FUSED) {
                float4 r = *(const float4*)(crow + j);
                o.x = fmaxf(r.x + o.x, 0.f);
                o.y = fmaxf(r.y + o.y, 0.f);
                o.z = fmaxf(r.z + o.z, 0.f);
                o.w = fmaxf(r.w + o.w, 0.f);
            }
            *(float4*)(crow + j) = o;
        }
    }
}

// ---------------- launch ----------------
extern "C" void kernel_launch(void* const* d_in, const int* in_sizes, int n_in,
                              void* d_out, int out_size) {
    const float* item_feat = (const float*)d_in[0];
    const float* pat_feat  = (const float*)d_in[1];
    const void*  iidx_raw  = d_in[2];
    const void*  pidx_raw  = d_in[3];
    const float* W_item = (const float*)d_in[4];
    const float* b_item = (const float*)d_in[5];
    const float* W_pat  = (const float*)d_in[6];
    const float* b_pat  = (const float*)d_in[7];
    const float* W_i2p  = (const float*)d_in[8];
    const float* b_i2p  = (const float*)d_in[9];
    const float* W_p2i  = (const float*)d_in[10];
    const float* b_p2i  = (const float*)d_in[11];

    const int N_ = in_sizes[0] / DI;
    const int M_ = in_sizes[1] / DI;
    const int E_ = in_sizes[2];

    float* h_item = (float*)d_out;                       // [N, H]
    float* h_pat  = (float*)d_out + (size_t)N_ * H;      // [M, H]

    void *pmsg_p = nullptr, *imsg_p = nullptr, *iidx_p = nullptr, *pidx_p = nullptr;
    cudaGetSymbolAddress(&pmsg_p, g_pmsg);
    cudaGetSymbolAddress(&imsg_p, g_imsg);
    cudaGetSymbolAddress(&iidx_p, g_iidx);
    cudaGetSymbolAddress(&pidx_p, g_pidx);
    float* pmsg = (float*)pmsg_p;
    float* imsg = (float*)imsg_p;
    int* iidx = (int*)iidx_p;
    int* pidx = (int*)pidx_p;

    // decode indices (int64 vs int32 auto-detect)
    int nsamp = E_ / 2 < 1024 ? E_ / 2 : 1024;
    detect_kernel<<<1, 256>>>((const unsigned long long*)iidx_raw, nsamp);
    convert_kernel<<<(E_ + 255) / 256, 256>>>(iidx_raw, pidx_raw, E_);

    // input encoders
    gemm_kernel<DI, false><<<(N_ + 127) / 128, 256>>>(item_feat, W_item, b_item, h_item, N_);
    gemm_kernel<DI, false><<<(M_ + 127) / 128, 256>>>(pat_feat,  W_pat,  b_pat,  h_pat,  M_);

    const int pmsg4 = M_ * H / 4;
    const int imsg4 = N_ * H / 4;
    const int scat_blocks = (E_ * 32 + 255) / 256;

    for (int r = 0; r < 2; r++) {
        // item -> pattern
        zero_kernel<<<(pmsg4 + 255) / 256, 256>>>(pmsg, pmsg4);
        scatter_kernel<<<scat_blocks, 256>>>(h_item, pmsg, iidx, pidx, E_);
        gemm_kernel<H, true><<<(M_ + 127) / 128, 256>>>(pmsg, W_i2p, b_i2p, h_pat, M_);
        // pattern -> item
        zero_kernel<<<(imsg4 + 255) / 256, 256>>>(imsg, imsg4);
        scatter_kernel<<<scat_blocks, 256>>>(h_pat, imsg, pidx, iidx, E_);
        gemm_kernel<H, true><<<(N_ + 127) / 128, 256>>>(imsg, W_p2i, b_p2i, h_item, N_);
    }
}

// round 2
// speedup vs baseline: 1.5466x; 1.5466x over previous
#include <cuda_runtime.h>
#include <cuda_bf16.h>
#include <cstdint>

#define H 128
#define DI 64
#define MAX_N 50000
#define MAX_M 20000
#define MAX_E 1000000
#define SCAN_B 512

// ---------------- scratch (no allocations allowed) ----------------
__device__ float g_pmsg[MAX_M * H];        // 10.24 MB
__device__ float g_imsg[MAX_N * H];        // 25.6 MB
__device__ int   g_psrc[MAX_E];            // item idx grouped by pattern
__device__ int   g_isrc[MAX_E];            // pattern idx grouped by item
__device__ int   g_prow[MAX_M + 1];
__device__ int   g_irow[MAX_N + 1];
__device__ int   g_pcur[MAX_M];
__device__ int   g_icur[MAX_N];
__device__ int   g_pcnt[MAX_M];
__device__ int   g_icnt[MAX_N];
__device__ int   g_pbsum[(MAX_M + SCAN_B - 1) / SCAN_B];
__device__ int   g_ibsum[(MAX_N + SCAN_B - 1) / SCAN_B];
__device__ int   g_is64;

// ---------------- index dtype detection ----------------
// int64 indices < 2^32 -> every high word is 0; int32 data makes "high words"
// be real indices, ~always nonzero. Deterministic for fixed input data.
__global__ void detect_kernel(const unsigned long long* __restrict__ raw, int nsamp) {
    __shared__ int any;
    if (threadIdx.x == 0) any = 0;
    __syncthreads();
    int found = 0;
    for (int i = threadIdx.x; i < nsamp; i += blockDim.x)
        if ((raw[i] >> 32) != 0ULL) found = 1;
    if (found) atomicExch(&any, 1);
    __syncthreads();
    if (threadIdx.x == 0) g_is64 = any ? 0 : 1;
}

__device__ __forceinline__ int load_idx(const void* raw, int e, int is64) {
    return is64 ? (int)((const long long*)raw)[e] : ((const int*)raw)[e];
}

// ---------------- CSR build ----------------
__global__ void zero_int_kernel(int* __restrict__ a, int n) {
    int i = blockIdx.x * blockDim.x + threadIdx.x;
    if (i < n) a[i] = 0;
}

__global__ void count_kernel(const void* __restrict__ iraw,
                             const void* __restrict__ praw, int E) {
    int e = blockIdx.x * blockDim.x + threadIdx.x;
    if (e >= E) return;
    int is64 = g_is64;
    int s = load_idx(iraw, e, is64);
    int d = load_idx(praw, e, is64);
    atomicAdd(&g_icnt[s], 1);
    atomicAdd(&g_pcnt[d], 1);
}

// per-block sums of counts
__global__ void reduce_counts_kernel(const int* __restrict__ cnt, int n,
                                     int* __restrict__ bsum) {
    __shared__ int sh[SCAN_B];
    int t = threadIdx.x;
    int i = blockIdx.x * SCAN_B + t;
    sh[t] = (i < n) ? cnt[i] : 0;
    __syncthreads();
    for (int s = SCAN_B / 2; s > 0; s >>= 1) {
        if (t < s) sh[t] += sh[t + s];
        __syncthreads();
    }
    if (t == 0) bsum[blockIdx.x] = sh[0];
}

// exclusive scan of block sums (single block, nb <= 1024)
__global__ void scan_bsums_kernel(int* __restrict__ bsum, int nb) {
    __shared__ int sh[1024];
    int t = threadIdx.x;
    int v = (t < nb) ? bsum[t] : 0;
    sh[t] = v;
    __syncthreads();
    for (int off = 1; off < 1024; off <<= 1) {
        int x = (t >= off) ? sh[t - off] : 0;
        __syncthreads();
        sh[t] += x;
        __syncthreads();
    }
    if (t < nb) bsum[t] = sh[t] - v;   // exclusive
}

// exclusive scan within block + block offset -> row_ptr, cursor
__global__ void scan_counts_kernel(const int* __restrict__ cnt, int n,
                                   const int* __restrict__ bsum,
                                   int* __restrict__ rowptr,
                                   int* __restrict__ cursor, int E) {
    __shared__ int sh[SCAN_B];
    int t = threadIdx.x;
    int i = blockIdx.x * SCAN_B + t;
    int v = (i < n) ? cnt[i] : 0;
    sh[t] = v;
    __syncthreads();
    for (int off = 1; off < SCAN_B; off <<= 1) {
        int x = (t >= off) ? sh[t - off] : 0;
        __syncthreads();
        sh[t] += x;
        __syncthreads();
    }
    int excl = sh[t] - v + bsum[blockIdx.x];
    if (i < n) { rowptr[i] = excl; cursor[i] = excl; }
    if (i == 0 && blockIdx.x == 0) rowptr[n] = E;
}

// place both CSRs in one pass over the edges
__global__ void place_kernel(const void* __restrict__ iraw,
                             const void* __restrict__ praw, int E) {
    int e = blockIdx.x * blockDim.x + threadIdx.x;
    if (e >= E) return;
    int is64 = g_is64;
    int s = load_idx(iraw, e, is64);   // item
    int d = load_idx(praw, e, is64);   // pattern
    int pp = atomicAdd(&g_pcur[d], 1);
    g_psrc[pp] = s;
    int ip = atomicAdd(&g_icur[s], 1);
    g_isrc[ip] = d;
}

// ---------------- segmented gather-reduce: dst[d] = sum src[srcids[e]] ----------------
// one warp per destination row, lanes cover H=128 as float4; no atomics, no pre-zero
__global__ __launch_bounds__(256)
void aggregate_kernel(const float* __restrict__ src, float* __restrict__ dst,
                      const int* __restrict__ row, const int* __restrict__ srcids,
                      int ndst) {
    int w = (int)((blockIdx.x * blockDim.x + threadIdx.x) >> 5);
    if (w >= ndst) return;
    int lane = threadIdx.x & 31;
    int beg = __ldg(row + w);
    int end = __ldg(row + w + 1);
    const float* sp = src + lane * 4;

    float4 a0 = make_float4(0.f, 0.f, 0.f, 0.f);
    float4 a1 = make_float4(0.f, 0.f, 0.f, 0.f);
    int e = beg;
    for (; e + 1 < end; e += 2) {
        int s0 = __ldg(srcids + e);
        int s1 = __ldg(srcids + e + 1);
        float4 v0 = *(const float4*)(sp + (size_t)s0 * H);
        float4 v1 = *(const float4*)(sp + (size_t)s1 * H);
        a0.x += v0.x; a0.y += v0.y; a0.z += v0.z; a0.w += v0.w;
        a1.x += v1.x; a1.y += v1.y; a1.z += v1.z; a1.w += v1.w;
    }
    if (e < end) {
        int s0 = __ldg(srcids + e);
        float4 v0 = *(const float4*)(sp + (size_t)s0 * H);
        a0.x += v0.x; a0.y += v0.y; a0.z += v0.z; a0.w += v0.w;
    }
    a0.x += a1.x; a0.y += a1.y; a0.z += a1.z; a0.w += a1.w;
    *(float4*)(dst + (size_t)w * H + lane * 4) = a0;
}

// ---------------- SGEMM: C = relu(A[n,K] @ W[K,128] + b)   (FUSED: relu(C + that)) ----------------
template<int K, bool FUSED>
__global__ __launch_bounds__(256, 2)
void gemm_kernel(const float* __restrict__ A, const float* __restrict__ W,
                 const float* __restrict__ bias, float* __restrict__ C, int n) {
    constexpr int BM = 128, BK = 16;
    __shared__ float As[BK][BM + 4];
    __shared__ float Ws[BK][H];

    const int tid = threadIdx.x;
    const int row0 = blockIdx.x * BM;
    const int tx = tid & 15;
    const int ty = tid >> 4;

    float acc[8][8];
#pragma unroll
    for (int i = 0; i < 8; i++)
#pragma unroll
        for (int j = 0; j < 8; j++) acc[i][j] = 0.f;

    for (int k0 = 0; k0 < K; k0 += BK) {
#pragma unroll
        for (int l = 0; l < 2; l++) {
            int f = tid + l * 256;
            int r = f >> 2;
            int c4 = f & 3;
            int grow = row0 + r;
            float4 v = make_float4(0.f, 0.f, 0.f, 0.f);
            if (grow < n)
                v = *(const float4*)(A + (size_t)grow * K + k0 + c4 * 4);
            As[c4 * 4 + 0][r] = v.x;
            As[c4 * 4 + 1][r] = v.y;
            As[c4 * 4 + 2][r] = v.z;
            As[c4 * 4 + 3][r] = v.w;
        }
#pragma unroll
        for (int l = 0; l < 2; l++) {
            int f = tid + l * 256;
            int r = f >> 5;
            int c4 = f & 31;
            *(float4*)&Ws[r][c4 * 4] = *(const float4*)(W + (size_t)(k0 + r) * H + c4 * 4);
        }
        __syncthreads();

#pragma unroll
        for (int k = 0; k < BK; k++) {
            float a[8], w[8];
            *(float4*)&a[0] = *(const float4*)&As[k][ty * 8 + 0];
            *(float4*)&a[4] = *(const float4*)&As[k][ty * 8 + 4];
            *(float4*)&w[0] = *(const float4*)&Ws[k][tx * 8 + 0];
            *(float4*)&w[4] = *(const float4*)&Ws[k][tx * 8 + 4];
#pragma unroll
            for (int i = 0; i < 8; i++)
#pragma unroll
                for (int j = 0; j < 8; j++)
                    acc[i][j] = fmaf(a[i], w[j], acc[i][j]);
        }
        __syncthreads();
    }

    float bj[8];
    *(float4*)&bj[0] = *(const float4*)&bias[tx * 8 + 0];
    *(float4*)&bj[4] = *(const float4*)&bias[tx * 8 + 4];
#pragma unroll
    for (int i = 0; i < 8; i++) {
        int grow = row0 + ty * 8 + i;
        if (grow >= n) continue;
        float* crow = C + (size_t)grow * H + tx * 8;
#pragma unroll
        for (int j = 0; j < 8; j += 4) {
            float4 o;
            o.x = fmaxf(acc[i][j + 0] + bj[j + 0], 0.f);
            o.y = fmaxf(acc[i][j + 1] + bj[j + 1], 0.f);
            o.z = fmaxf(acc[i][j + 2] + bj[j + 2], 0.f);
            o.w = fmaxf(acc[i][j + 3] + bj[j + 3], 0.f);
            if (FUSED) {
                float4 r = *(const float4*)(crow + j);
                o.x = fmaxf(r.x + o.x, 0.f);
                o.y = fmaxf(r.y + o.y, 0.f);
                o.z = fmaxf(r.z + o.z, 0.f);
                o.w = fmaxf(r.w + o.w, 0.f);
            }
            *(float4*)(crow + j) = o;
        }
    }
}

// ---------------- launch ----------------
extern "C" void kernel_launch(void* const* d_in, const int* in_sizes, int n_in,
                              void* d_out, int out_size) {
    const float* item_feat = (const float*)d_in[0];
    const float* pat_feat  = (const float*)d_in[1];
    const void*  iidx_raw  = d_in[2];
    const void*  pidx_raw  = d_in[3];
    const float* W_item = (const float*)d_in[4];
    const float* b_item = (const float*)d_in[5];
    const float* W_pat  = (const float*)d_in[6];
    const float* b_pat  = (const float*)d_in[7];
    const float* W_i2p  = (const float*)d_in[8];
    const float* b_i2p  = (const float*)d_in[9];
    const float* W_p2i  = (const float*)d_in[10];
    const float* b_p2i  = (const float*)d_in[11];

    const int N_ = in_sizes[0] / DI;
    const int M_ = in_sizes[1] / DI;
    const int E_ = in_sizes[2];

    float* h_item = (float*)d_out;
    float* h_pat  = (float*)d_out + (size_t)N_ * H;

    void *p;
    cudaGetSymbolAddress(&p, g_pmsg);  float* pmsg  = (float*)p;
    cudaGetSymbolAddress(&p, g_imsg);  float* imsg  = (float*)p;
    cudaGetSymbolAddress(&p, g_psrc);  int* psrc  = (int*)p;
    cudaGetSymbolAddress(&p, g_isrc);  int* isrc  = (int*)p;
    cudaGetSymbolAddress(&p, g_prow);  int* prow  = (int*)p;
    cudaGetSymbolAddress(&p, g_irow);  int* irow  = (int*)p;
    cudaGetSymbolAddress(&p, g_pcur);  int* pcur  = (int*)p;
    cudaGetSymbolAddress(&p, g_icur);  int* icur  = (int*)p;
    cudaGetSymbolAddress(&p, g_pcnt);  int* pcnt  = (int*)p;
    cudaGetSymbolAddress(&p, g_icnt);  int* icnt  = (int*)p;
    cudaGetSymbolAddress(&p, g_pbsum); int* pbsum = (int*)p;
    cudaGetSymbolAddress(&p, g_ibsum); int* ibsum = (int*)p;

    const int pblocks = (M_ + SCAN_B - 1) / SCAN_B;
    const int iblocks = (N_ + SCAN_B - 1) / SCAN_B;

    // ---- CSR build (once per launch, reused both rounds) ----
    int nsamp = E_ / 2 < 1024 ? E_ / 2 : 1024;
    detect_kernel<<<1, 256>>>((const unsigned long long*)iidx_raw, nsamp);
    zero_int_kernel<<<(M_ + 255) / 256, 256>>>(pcnt, M_);
    zero_int_kernel<<<(N_ + 255) / 256, 256>>>(icnt, N_);
    count_kernel<<<(E_ + 255) / 256, 256>>>(iidx_raw, pidx_raw, E_);

    reduce_counts_kernel<<<pblocks, SCAN_B>>>(pcnt, M_, pbsum);
    scan_bsums_kernel<<<1, 1024>>>(pbsum, pblocks);
    scan_counts_kernel<<<pblocks, SCAN_B>>>(pcnt, M_, pbsum, prow, pcur, E_);

    reduce_counts_kernel<<<iblocks, SCAN_B>>>(icnt, N_, ibsum);
    scan_bsums_kernel<<<1, 1024>>>(ibsum, iblocks);
    scan_counts_kernel<<<iblocks, SCAN_B>>>(icnt, N_, ibsum, irow, icur, E_);

    place_kernel<<<(E_ + 255) / 256, 256>>>(iidx_raw, pidx_raw, E_);

    // ---- input encoders ----
    gemm_kernel<DI, false><<<(N_ + 127) / 128, 256>>>(item_feat, W_item, b_item, h_item, N_);
    gemm_kernel<DI, false><<<(M_ + 127) / 128, 256>>>(pat_feat,  W_pat,  b_pat,  h_pat,  M_);

    const int pagg_blocks = (M_ * 32 + 255) / 256;
    const int iagg_blocks = (N_ * 32 + 255) / 256;

    for (int r = 0; r < 2; r++) {
        // item -> pattern
        aggregate_kernel<<<pagg_blocks, 256>>>(h_item, pmsg, prow, psrc, M_);
        gemm_kernel<H, true><<<(M_ + 127) / 128, 256>>>(pmsg, W_i2p, b_i2p, h_pat, M_);
        // pattern -> item
        aggregate_kernel<<<iagg_blocks, 256>>>(h_pat, imsg, irow, isrc, N_);
        gemm_kernel<H, true><<<(N_ + 127) / 128, 256>>>(imsg, W_p2i, b_p2i, h_item, N_);
    }
}

// round 4
// speedup vs baseline: 1.7917x; 1.1585x over previous
#include <cuda_runtime.h>
#include <cstdint>

#define H 128
#define DI 64
#define MAX_N 50000
#define MAX_M 20000
#define MAX_E 1000000
#define SCAN_B 512

// ---------------- scratch (no allocations allowed) ----------------
__device__ float g_pmsg[MAX_M * H];
__device__ float g_imsg[MAX_N * H];
__device__ float g_whi[4 * H * H];   // tf32-hi of: item, pat, i2p, p2i
__device__ float g_wlo[4 * H * H];   // tf32-lo
__device__ int   g_psrc[MAX_E];
__device__ int   g_isrc[MAX_E];
__device__ int   g_prow[MAX_M + 1];
__device__ int   g_irow[MAX_N + 1];
__device__ int   g_pcur[MAX_M];
__device__ int   g_icur[MAX_N];
__device__ int   g_pcnt[MAX_M];
__device__ int   g_icnt[MAX_N];
__device__ int   g_pbsum[(MAX_M + SCAN_B - 1) / SCAN_B];
__device__ int   g_ibsum[(MAX_N + SCAN_B - 1) / SCAN_B];
__device__ int   g_is64;

// ---------------- index dtype detection ----------------
__global__ void detect_kernel(const unsigned long long* __restrict__ raw, int nsamp) {
    __shared__ int any;
    if (threadIdx.x == 0) any = 0;
    __syncthreads();
    int found = 0;
    for (int i = threadIdx.x; i < nsamp; i += blockDim.x)
        if ((raw[i] >> 32) != 0ULL) found = 1;
    if (found) atomicExch(&any, 1);
    __syncthreads();
    if (threadIdx.x == 0) g_is64 = any ? 0 : 1;
}

__device__ __forceinline__ int load_idx(const void* raw, int e, int is64) {
    return is64 ? (int)((const long long*)raw)[e] : ((const int*)raw)[e];
}

// ---------------- CSR build ----------------
__global__ void zero_int_kernel(int* __restrict__ a, int n) {
    int i = blockIdx.x * blockDim.x + threadIdx.x;
    if (i < n) a[i] = 0;
}

__global__ void count_kernel(const void* __restrict__ iraw,
                             const void* __restrict__ praw, int E) {
    int e = blockIdx.x * blockDim.x + threadIdx.x;
    if (e >= E) return;
    int is64 = g_is64;
    atomicAdd(&g_icnt[load_idx(iraw, e, is64)], 1);
    atomicAdd(&g_pcnt[load_idx(praw, e, is64)], 1);
}

__global__ void reduce_counts_kernel(const int* __restrict__ cnt, int n,
                                     int* __restrict__ bsum) {
    __shared__ int sh[SCAN_B];
    int t = threadIdx.x;
    int i = blockIdx.x * SCAN_B + t;
    sh[t] = (i < n) ? cnt[i] : 0;
    __syncthreads();
    for (int s = SCAN_B / 2; s > 0; s >>= 1) {
        if (t < s) sh[t] += sh[t + s];
        __syncthreads();
    }
    if (t == 0) bsum[blockIdx.x] = sh[0];
}

__global__ void scan_bsums_kernel(int* __restrict__ bsum, int nb) {
    __shared__ int sh[1024];
    int t = threadIdx.x;
    int v = (t < nb) ? bsum[t] : 0;
    sh[t] = v;
    __syncthreads();
    for (int off = 1; off < 1024; off <<= 1) {
        int x = (t >= off) ? sh[t - off] : 0;
        __syncthreads();
        sh[t] += x;
        __syncthreads();
    }
    if (t < nb) bsum[t] = sh[t] - v;
}

__global__ void scan_counts_kernel(const int* __restrict__ cnt, int n,
                                   const int* __restrict__ bsum,
                                   int* __restrict__ rowptr,
                                   int* __restrict__ cursor, int E) {
    __shared__ int sh[SCAN_B];
    int t = threadIdx.x;
    int i = blockIdx.x * SCAN_B + t;
    int v = (i < n) ? cnt[i] : 0;
    sh[t] = v;
    __syncthreads();
    for (int off = 1; off < SCAN_B; off <<= 1) {
        int x = (t >= off) ? sh[t - off] : 0;
        __syncthreads();
        sh[t] += x;
        __syncthreads();
    }
    int excl = sh[t] - v + bsum[blockIdx.x];
    if (i < n) { rowptr[i] = excl; cursor[i] = excl; }
    if (i == 0 && blockIdx.x == 0) rowptr[n] = E;
}

__global__ void place_kernel(const void* __restrict__ iraw,
                             const void* __restrict__ praw, int E) {
    int e = blockIdx.x * blockDim.x + threadIdx.x;
    if (e >= E) return;
    int is64 = g_is64;
    int s = load_idx(iraw, e, is64);
    int d = load_idx(praw, e, is64);
    g_psrc[atomicAdd(&g_pcur[d], 1)] = s;
    g_isrc[atomicAdd(&g_icur[s], 1)] = d;
}

// ---------------- weight split: W -> tf32 hi + tf32 lo ----------------
__device__ __forceinline__ uint32_t to_tf32(float x) {
    uint32_t r;
    asm("cvt.rna.tf32.f32 %0, %1;" : "=r"(r) : "f"(x));
    return r;
}

__global__ void wsplit_kernel(const float* __restrict__ W,
                              float* __restrict__ hi, float* __restrict__ lo, int n) {
    int i = blockIdx.x * blockDim.x + threadIdx.x;
    if (i >= n) return;
    float w = W[i];
    float h = __uint_as_float(to_tf32(w));
    hi[i] = h;
    lo[i] = __uint_as_float(to_tf32(w - h));
}

// ---------------- segmented gather-reduce (fp32) ----------------
__global__ __launch_bounds__(256)
void aggregate_kernel(const float* __restrict__ src, float* __restrict__ dst,
                      const int* __restrict__ row, const int* __restrict__ srcids,
                      int ndst) {
    int w = (int)((blockIdx.x * blockDim.x + threadIdx.x) >> 5);
    if (w >= ndst) return;
    int lane = threadIdx.x & 31;
    int beg = __ldg(row + w);
    int end = __ldg(row + w + 1);
    const float* sp = src + lane * 4;

    float4 a0 = make_float4(0.f, 0.f, 0.f, 0.f);
    float4 a1 = make_float4(0.f, 0.f, 0.f, 0.f);
    int e = beg;
    for (; e + 1 < end; e += 2) {
        int s0 = __ldg(srcids + e);
        int s1 = __ldg(srcids + e + 1);
        float4 v0 = *(const float4*)(sp + (size_t)s0 * H);
        float4 v1 = *(const float4*)(sp + (size_t)s1 * H);
        a0.x += v0.x; a0.y += v0.y; a0.z += v0.z; a0.w += v0.w;
        a1.x += v1.x; a1.y += v1.y; a1.z += v1.z; a1.w += v1.w;
    }
    if (e < end) {
        float4 v0 = *(const float4*)(sp + (size_t)__ldg(srcids + e) * H);
        a0.x += v0.x; a0.y += v0.y; a0.z += v0.z; a0.w += v0.w;
    }
    a0.x += a1.x; a0.y += a1.y; a0.z += a1.z; a0.w += a1.w;
    *(float4*)(dst + (size_t)w * H + lane * 4) = a0;
}

// ---------------- 3xTF32 GEMM: C = relu(A[n,K] @ W[K,128] + b); FUSED: relu(C + that) ----------------
template<int K, bool FUSED>
__global__ __launch_bounds__(256, 2)
void tgemm_kernel(const float* __restrict__ A,
                  const float* __restrict__ Whi, const float* __restrict__ Wlo,
                  const float* __restrict__ bias, float* __restrict__ C, int n) {
    constexpr int BM = 128, BN = 128, BK = 16;
    __shared__ float As[BM][20];      // stride 20: conflict-free frag lds
    __shared__ float BsH[BK][136];    // stride 136 (mod32=8): conflict-free
    __shared__ float BsL[BK][136];

    const int tid = threadIdx.x;
    const int wid = tid >> 5, lane = tid & 31;
    const int wr = wid >> 1;          // m offset wr*32
    const int wc = wid & 1;           // n offset wc*64
    const int row0 = blockIdx.x * BM;
    const int l4 = lane >> 2, lm = lane & 3;

    float acc[2][8][4];
#pragma unroll
    for (int mi = 0; mi < 2; mi++)
#pragma unroll
        for (int nj = 0; nj < 8; nj++)
#pragma unroll
            for (int q = 0; q < 4; q++) acc[mi][nj][q] = 0.f;

    for (int k0 = 0; k0 < K; k0 += BK) {
        // A tile: 128x16 fp32 = 512 float4
#pragma unroll
        for (int i = 0; i < 2; i++) {
            int f = tid + i * 256;
            int r = f >> 2, c4 = (f & 3) * 4;
            int gr = row0 + r;
            float4 v = make_float4(0.f, 0.f, 0.f, 0.f);
            if (gr < n) v = *(const float4*)(A + (size_t)gr * K + k0 + c4);
            *(float4*)&As[r][c4] = v;
        }
        // B tiles hi/lo: 16x128 each
#pragma unroll
        for (int i = 0; i < 2; i++) {
            int f = tid + i * 256;
            int r = f >> 5, c4 = (f & 31) * 4;
            *(float4*)&BsH[r][c4] = *(const float4*)(Whi + (size_t)(k0 + r) * BN + c4);
            *(float4*)&BsL[r][c4] = *(const float4*)(Wlo + (size_t)(k0 + r) * BN + c4);
        }
        __syncthreads();

#pragma unroll
        for (int ks = 0; ks < 2; ks++) {
            const int kb = ks * 8 + lm;
            // A fragments + in-register tf32 split
            uint32_t ah[2][4], al[2][4];
#pragma unroll
            for (int mi = 0; mi < 2; mi++) {
                int rb = wr * 32 + mi * 16 + l4;
                float av[4];
                av[0] = As[rb][kb];
                av[1] = As[rb + 8][kb];
                av[2] = As[rb][kb + 4];
                av[3] = As[rb + 8][kb + 4];
#pragma unroll
                for (int q = 0; q < 4; q++) {
                    uint32_t hb = to_tf32(av[q]);
                    ah[mi][q] = hb;
                    al[mi][q] = to_tf32(av[q] - __uint_as_float(hb));
                }
            }
#pragma unroll
            for (int nj = 0; nj < 8; nj++) {
                int nn = wc * 64 + nj * 8 + l4;
                uint32_t bh0 = __float_as_uint(BsH[kb][nn]);
                uint32_t bh1 = __float_as_uint(BsH[kb + 4][nn]);
                uint32_t bl0 = __float_as_uint(BsL[kb][nn]);
                uint32_t bl1 = __float_as_uint(BsL[kb + 4][nn]);
#pragma unroll
                for (int mi = 0; mi < 2; mi++) {
                    float* d = acc[mi][nj];
#define TMMA(A0,A1,A2,A3,B0,B1) \
    asm volatile("mma.sync.aligned.m16n8k8.row.col.f32.tf32.tf32.f32 " \
        "{%0,%1,%2,%3},{%4,%5,%6,%7},{%8,%9},{%0,%1,%2,%3};" \
        : "+f"(d[0]), "+f"(d[1]), "+f"(d[2]), "+f"(d[3]) \
        : "r"(A0), "r"(A1), "r"(A2), "r"(A3), "r"(B0), "r"(B1))
                    TMMA(ah[mi][0], ah[mi][1], ah[mi][2], ah[mi][3], bh0, bh1);
                    TMMA(al[mi][0], al[mi][1], al[mi][2], al[mi][3], bh0, bh1);
                    TMMA(ah[mi][0], ah[mi][1], ah[mi][2], ah[mi][3], bl0, bl1);
#undef TMMA
                }
            }
        }
        __syncthreads();
    }

    // epilogue: c0,c1 -> row l4, cols lm*2,+1 ; c2,c3 -> row l4+8
#pragma unroll
    for (int mi = 0; mi < 2; mi++) {
#pragma unroll
        for (int hh = 0; hh < 2; hh++) {
            int r = row0 + wr * 32 + mi * 16 + l4 + hh * 8;
            if (r >= n) continue;
#pragma unroll
            for (int nj = 0; nj < 8; nj++) {
                int cc = wc * 64 + nj * 8 + lm * 2;
                float x0 = fmaxf(acc[mi][nj][hh * 2 + 0] + __ldg(bias + cc), 0.f);
                float x1 = fmaxf(acc[mi][nj][hh * 2 + 1] + __ldg(bias + cc + 1), 0.f);
                if (FUSED) {
                    float2 rv = *(const float2*)(C + (size_t)r * BN + cc);
                    x0 = fmaxf(rv.x + x0, 0.f);
                    x1 = fmaxf(rv.y + x1, 0.f);
                }
                *(float2*)(C + (size_t)r * BN + cc) = make_float2(x0, x1);
            }
        }
    }
}

// ---------------- launch ----------------
extern "C" void kernel_launch(void* const* d_in, const int* in_sizes, int n_in,
                              void* d_out, int out_size) {
    const float* item_feat = (const float*)d_in[0];
    const float* pat_feat  = (const float*)d_in[1];
    const void*  iidx_raw  = d_in[2];
    const void*  pidx_raw  = d_in[3];
    const float* W_item = (const float*)d_in[4];
    const float* b_item = (const float*)d_in[5];
    const float* W_pat  = (const float*)d_in[6];
    const float* b_pat  = (const float*)d_in[7];
    const float* W_i2p  = (const float*)d_in[8];
    const float* b_i2p  = (const float*)d_in[9];
    const float* W_p2i  = (const float*)d_in[10];
    const float* b_p2i  = (const float*)d_in[11];

    const int N_ = in_sizes[0] / DI;
    const int M_ = in_sizes[1] / DI;
    const int E_ = in_sizes[2];

    float* h_item = (float*)d_out;
    float* h_pat  = (float*)d_out + (size_t)N_ * H;

    void* p;
    cudaGetSymbolAddress(&p, g_pmsg);  float* pmsg = (float*)p;
    cudaGetSymbolAddress(&p, g_imsg);  float* imsg = (float*)p;
    cudaGetSymbolAddress(&p, g_whi);   float* whi  = (float*)p;
    cudaGetSymbolAddress(&p, g_wlo);   float* wlo  = (float*)p;
    cudaGetSymbolAddress(&p, g_psrc);  int* psrc  = (int*)p;
    cudaGetSymbolAddress(&p, g_isrc);  int* isrc  = (int*)p;
    cudaGetSymbolAddress(&p, g_prow);  int* prow  = (int*)p;
    cudaGetSymbolAddress(&p, g_irow);  int* irow  = (int*)p;
    cudaGetSymbolAddress(&p, g_pcnt);  int* pcnt  = (int*)p;
    cudaGetSymbolAddress(&p, g_icnt);  int* icnt  = (int*)p;
    cudaGetSymbolAddress(&p, g_pbsum); int* pbsum = (int*)p;
    cudaGetSymbolAddress(&p, g_ibsum); int* ibsum = (int*)p;
    cudaGetSymbolAddress(&p, g_pcur);  int* pcur  = (int*)p;
    cudaGetSymbolAddress(&p, g_icur);  int* icur  = (int*)p;

    float* wi_hi  = whi;                float* wi_lo  = wlo;                // item  64x128
    float* wp_hi  = whi + 1 * H * H;    float* wp_lo  = wlo + 1 * H * H;    // pat   64x128
    float* w2p_hi = whi + 2 * H * H;    float* w2p_lo = wlo + 2 * H * H;    // i2p  128x128
    float* w2i_hi = whi + 3 * H * H;    float* w2i_lo = wlo + 3 * H * H;    // p2i  128x128

    const int pblocks = (M_ + SCAN_B - 1) / SCAN_B;
    const int iblocks = (N_ + SCAN_B - 1) / SCAN_B;

    // ---- CSR build ----
    int nsamp = E_ / 2 < 1024 ? E_ / 2 : 1024;
    detect_kernel<<<1, 256>>>((const unsigned long long*)iidx_raw, nsamp);
    zero_int_kernel<<<(M_ + 255) / 256, 256>>>(pcnt, M_);
    zero_int_kernel<<<(N_ + 255) / 256, 256>>>(icnt, N_);
    count_kernel<<<(E_ + 255) / 256, 256>>>(iidx_raw, pidx_raw, E_);
    reduce_counts_kernel<<<pblocks, SCAN_B>>>(pcnt, M_, pbsum);
    scan_bsums_kernel<<<1, 1024>>>(pbsum, pblocks);
    scan_counts_kernel<<<pblocks, SCAN_B>>>(pcnt, M_, pbsum, prow, pcur, E_);
    reduce_counts_kernel<<<iblocks, SCAN_B>>>(icnt, N_, ibsum);
    scan_bsums_kernel<<<1, 1024>>>(ibsum, iblocks);
    scan_counts_kernel<<<iblocks, SCAN_B>>>(icnt, N_, ibsum, irow, icur, E_);
    place_kernel<<<(E_ + 255) / 256, 256>>>(iidx_raw, pidx_raw, E_);

    // ---- weight splits ----
    wsplit_kernel<<<(DI * H + 255) / 256, 256>>>(W_item, wi_hi,  wi_lo,  DI * H);
    wsplit_kernel<<<(DI * H + 255) / 256, 256>>>(W_pat,  wp_hi,  wp_lo,  DI * H);
    wsplit_kernel<<<(H * H + 255) / 256, 256>>>(W_i2p,  w2p_hi, w2p_lo, H * H);
    wsplit_kernel<<<(H * H + 255) / 256, 256>>>(W_p2i,  w2i_hi, w2i_lo, H * H);

    // ---- encoders ----
    tgemm_kernel<DI, false><<<(N_ + 127) / 128, 256>>>(item_feat, wi_hi, wi_lo, b_item, h_item, N_);
    tgemm_kernel<DI, false><<<(M_ + 127) / 128, 256>>>(pat_feat,  wp_hi, wp_lo, b_pat,  h_pat,  M_);

    const int pagg_blocks = (M_ * 32 + 255) / 256;
    const int iagg_blocks = (N_ * 32 + 255) / 256;

    for (int r = 0; r < 2; r++) {
        // item -> pattern
        aggregate_kernel<<<pagg_blocks, 256>>>(h_item, pmsg, prow, psrc, M_);
        tgemm_kernel<H, true><<<(M_ + 127) / 128, 256>>>(pmsg, w2p_hi, w2p_lo, b_i2p, h_pat, M_);
        // pattern -> item
        aggregate_kernel<<<iagg_blocks, 256>>>(h_pat, imsg, irow, isrc, N_);
        tgemm_kernel<H, true><<<(N_ + 127) / 128, 256>>>(imsg, w2i_hi, w2i_lo, b_p2i, h_item, N_);
    }
}